// round 11
// baseline (speedup 1.0000x reference)
#include <cuda_runtime.h>

// Shape: [1, 8, 8, 8, 258, 258, 1] fp32; 512 images of 258x258.
//
// Pass 1 (branchless stream, ONE divmod): out = remap_w(x) * hm.
//   w0 = idx % 258 (66564 = 258^2, so image offset vanishes mod 258).
//   258 % 4 == 2 -> w-edge sources are in-chunk permutes:
//     w0==0: lane0<-v.y   w0==254: lane3<-v.z   w0==256: lane1<-v.x, lane2<-v.w
//   h-edge rows get provisional values, fixed by pass 2.
//
// Pass 2 (vectorized row fixup, branchless, ~7MB traffic):
//   rewrites rows 0 / 257 of each image as float2:
//     own = x[row]  (for w-rule lanes, ORIGINAL h)
//     src = x[row==0 ? 1 : 256]  (h-rule lanes)
//     w2==0:   a = (own.y, src.y)     w2==128: a = (src.x, own.x)
//     else:    a = (src.x, src.y)
//   3 independent 8B loads per thread (MLP), fully coalesced.

#define HW        258u
#define IMG_ELEMS 66564u
#define TOTAL4    8520192u    // float4 chunks; 33282 * 256 exact

__global__ __launch_bounds__(256)
void halo_main_kernel(const float* __restrict__ x,
                      const float4* __restrict__ hm,
                      float4* __restrict__ out)
{
    unsigned i = blockIdx.x * 256u + threadIdx.x;   // exact cover
    unsigned idx = i * 4u;

    float4 v = __ldcs(reinterpret_cast<const float4*>(x + idx));
    float4 b = __ldcs(hm + i);

    unsigned w0 = idx % HW;   // 0..256, even — the only divmod

    float a0 = (w0 == 0u)      ? v.y : v.x;
    float a1 = (w0 == HW - 2u) ? v.x : v.y;
    float a2 = (w0 == HW - 2u) ? v.w : v.z;
    float a3 = (w0 == HW - 4u) ? v.z : v.w;

    float4 r;
    r.x = a0 * b.x;
    r.y = a1 * b.y;
    r.z = a2 * b.z;
    r.w = a3 * b.w;
    __stcs(out + i, r);
}

// 512 images * 2 rows * 129 float2 = 132,096 threads = 516 blocks * 256 exact.
#define ROW2   129u
#define FIXT   132096u

__global__ __launch_bounds__(256)
void halo_rowfix_kernel(const float* __restrict__ x,
                        const float* __restrict__ hm,
                        float* __restrict__ out)
{
    unsigned t = blockIdx.x * 256u + threadIdx.x;   // exact cover
    unsigned img = t / (2u * ROW2);
    unsigned r   = t - img * (2u * ROW2);
    bool     top = (r < ROW2);
    unsigned w2  = top ? r : r - ROW2;

    unsigned base    = img * IMG_ELEMS;
    unsigned own_off = base + (top ? 0u : (HW - 1u) * HW) + 2u * w2;
    int      srcadj  = top ? (int)HW : -(int)HW;    // row 1 / row 256

    // 3 independent coalesced 8B loads (front-batched).
    float2 own = *reinterpret_cast<const float2*>(x + own_off);
    float2 src = *reinterpret_cast<const float2*>(x + (int)own_off + srcadj);
    float2 m   = *reinterpret_cast<const float2*>(hm + own_off);

    float a0 = (w2 == 0u)        ? own.y : src.x;   // w-rule (orig h) at w==0
    float a1 = (w2 == ROW2 - 1u) ? own.x : src.y;   // w-rule (orig h) at w==257

    float2 o;
    o.x = a0 * m.x;
    o.y = a1 * m.y;
    *reinterpret_cast<float2*>(out + own_off) = o;
}

extern "C" void kernel_launch(void* const* d_in, const int* in_sizes, int n_in,
                              void* d_out, int out_size)
{
    const float* x  = (const float*)d_in[0];
    const float* hm = (const float*)d_in[1];
    float* out = (float*)d_out;

    halo_main_kernel<<<TOTAL4 / 256u, 256>>>(x, (const float4*)hm, (float4*)out);
    halo_rowfix_kernel<<<FIXT / 256u, 256>>>(x, hm, out);
}

// round 12
// speedup vs baseline: 1.0319x; 1.0319x over previous
#include <cuda_runtime.h>

// Shape: [1, 8, 8, 8, 258, 258, 1] fp32; 512 images of 258x258.
// 34,080,768 elems = 8,520,192 float4 chunks; grid 33282 x 256 exact.
//
// Single launch. Fast path (97.7% of blocks) = 1 per-thread divmod:
//   w0 = idx % 258  (66564 = 258^2, image offset vanishes mod 258)
//   258 % 4 == 2 -> w-edge sources are in-chunk permutes:
//     w0==0: lane0<-v.y   w0==254: lane3<-v.z   w0==256: lane1<-v.x, lane2<-v.w
// Edge detection is BLOCK-UNIFORM: a 1024-elem block can touch rows 0/257
// only if brem = (b*1024) % 66564 is < 258 or > 65280 (includes the straddle
// chunk at rem 66304 and image-boundary crossers). ~770 of 33282 blocks take
// the slow path; the branch is warp-uniform -> zero divergence elsewhere.
// Slow path = R10's proven per-thread predicated handling:
//   top=(rem<258) bot=(rem>=66306) sb=(rem==66304) tb=top|bot
//   u = x[idx +/- 258 .. +3] via 2 predicated 8B loads
//   lane0 = e0?v.y : tb?u0:v.x      lane1 = s?v.x : tb?u1:v.y
//   lane2 = s?v.w : tb?u2:v.z       lane3 = e4?v.z : (s?sb:tb)?u3:v.w

#define HW        258u
#define IMG_ELEMS 66564u
#define TOTAL4    8520192u

__global__ __launch_bounds__(256)
void halo_ublock_kernel(const float* __restrict__ x,
                        const float4* __restrict__ hm,
                        float4* __restrict__ out)
{
    unsigned b = blockIdx.x;
    unsigned i = b * 256u + threadIdx.x;   // exact cover
    unsigned idx = i * 4u;

    float4 v  = __ldcs(reinterpret_cast<const float4*>(x + idx));
    float4 bm = __ldcs(hm + i);

    unsigned w0 = idx % HW;                 // the only per-thread divmod (fast path)

    float a0 = (w0 == 0u)      ? v.y : v.x;
    float a1 = (w0 == HW - 2u) ? v.x : v.y;
    float a2 = (w0 == HW - 2u) ? v.w : v.z;
    float a3 = (w0 == HW - 4u) ? v.z : v.w;

    // Block-uniform edge test (uniform datapath; warp-uniform branch).
    unsigned brem = (b * 1024u) % IMG_ELEMS;
    if (brem < HW || brem > 65280u) {
        unsigned rem = idx % IMG_ELEMS;
        bool top = (rem < HW);
        bool bot = (rem >= 66306u);         // 257*258
        bool sb  = (rem == 66304u);         // straddle into row 257
        bool tb  = top | bot;
        if (tb | sb) {
            int D = top ? (int)HW : -(int)HW;
            const float* p = x + (int)idx + D;
            float2 ua = *reinterpret_cast<const float2*>(p);
            float2 ub = *reinterpret_cast<const float2*>(p + 2);
            bool e0 = (w0 == 0u), e4 = (w0 == HW - 4u), s = (w0 == HW - 2u);
            a0 = e0 ? v.y : (tb ? ua.x : v.x);
            a1 = s  ? v.x : (tb ? ua.y : v.y);
            a2 = s  ? v.w : (tb ? ub.x : v.z);
            a3 = e4 ? v.z : ((s ? sb : tb) ? ub.y : v.w);
        }
    }

    float4 r;
    r.x = a0 * bm.x;
    r.y = a1 * bm.y;
    r.z = a2 * bm.z;
    r.w = a3 * bm.w;
    __stcs(out + i, r);
}

extern "C" void kernel_launch(void* const* d_in, const int* in_sizes, int n_in,
                              void* d_out, int out_size)
{
    const float* x  = (const float*)d_in[0];
    const float* hm = (const float*)d_in[1];
    float* out = (float*)d_out;

    halo_ublock_kernel<<<TOTAL4 / 256u, 256>>>(x, (const float4*)hm, (float4*)out);
}

// round 13
// speedup vs baseline: 1.0416x; 1.0094x over previous
#include <cuda_runtime.h>

// Shape: [1, 8, 8, 8, 258, 258, 1] fp32; 512 images of 258x258.
// 34,080,768 elems = 8,520,192 float4 chunks; grid 33282 x 256 exact.
//
// Single launch, block-uniform specialization with a __noinline__ slow path
// so ptxas CANNOT hoist the mod-66564 into the fast stream (R12 failure mode).
//
// Fast path (97.7% of blocks), ONE per-thread divmod:
//   w0 = idx % 258 (66564 = 258^2 -> image offset vanishes mod 258)
//   258 % 4 == 2 -> w-edge sources are in-chunk permutes:
//     w0==0: lane0<-v.y   w0==254: lane3<-v.z   w0==256: lane1<-v.x, lane2<-v.w
//
// Edge blocks: brem = (b*1024) % 66564 in [0,258) or (65280, 66564).
//   (brem=65281 is the first block whose last elem reaches the straddle chunk
//    at rem 66304; chunks never cross images since 66564 % 4 == 0.)
// Slow path (R10 logic, verified per-corner):
//   top=(rem<258) bot=(rem>=66306) sb=(rem==66304) tb=top|bot
//   u = x[idx+D .. +3], D = +258 (top) / -258 (bot/sb), via 2x 8B loads
//   lane0=e0?v.y:tb?u0:v.x   lane1=s?v.x:tb?u1:v.y
//   lane2=s?v.w:tb?u2:v.z    lane3=e4?v.z:(s?sb:tb)?u3:v.w

#define HW        258u
#define IMG_ELEMS 66564u
#define TOTAL4    8520192u

__device__ __noinline__ static void halo_slow_block(
    const float* __restrict__ x,
    const float4* __restrict__ hm,
    float4* __restrict__ out,
    unsigned i)
{
    unsigned idx = i * 4u;

    float4 v  = __ldcs(reinterpret_cast<const float4*>(x + idx));
    float4 bm = __ldcs(hm + i);

    unsigned rem = idx % IMG_ELEMS;
    unsigned w0  = rem % HW;

    bool e0  = (w0 == 0u);
    bool e4  = (w0 == HW - 4u);
    bool s   = (w0 == HW - 2u);
    bool top = (rem < HW);
    bool bot = (rem >= 66306u);        // 257*258
    bool sb  = (rem == 66304u);        // straddle into row 257
    bool tb  = top | bot;

    float u0 = 0.f, u1 = 0.f, u2 = 0.f, u3 = 0.f;
    if (tb | sb) {
        int D = top ? (int)HW : -(int)HW;
        const float* p = x + (int)idx + D;
        float2 ua = *reinterpret_cast<const float2*>(p);
        float2 ub = *reinterpret_cast<const float2*>(p + 2);
        u0 = ua.x; u1 = ua.y; u2 = ub.x; u3 = ub.y;
    }

    float a0 = e0 ? v.y : (tb ? u0 : v.x);
    float a1 = s  ? v.x : (tb ? u1 : v.y);
    float a2 = s  ? v.w : (tb ? u2 : v.z);
    float a3 = e4 ? v.z : ((s ? sb : tb) ? u3 : v.w);

    float4 r;
    r.x = a0 * bm.x;
    r.y = a1 * bm.y;
    r.z = a2 * bm.z;
    r.w = a3 * bm.w;
    __stcs(out + i, r);
}

__global__ __launch_bounds__(256)
void halo_call_kernel(const float* __restrict__ x,
                      const float4* __restrict__ hm,
                      float4* __restrict__ out)
{
    unsigned b = blockIdx.x;
    unsigned i = b * 256u + threadIdx.x;   // exact cover

    // Block-uniform edge test; slow path sealed behind a call.
    unsigned brem = (b * 1024u) % IMG_ELEMS;
    if (brem < HW || brem > 65280u) {
        halo_slow_block(x, hm, out, i);
        return;
    }

    // ---- fast path: pure 1-divmod branchless stream ----
    unsigned idx = i * 4u;
    float4 v  = __ldcs(reinterpret_cast<const float4*>(x + idx));
    float4 bm = __ldcs(hm + i);

    unsigned w0 = idx % HW;   // 0..256, even

    float a0 = (w0 == 0u)      ? v.y : v.x;
    float a1 = (w0 == HW - 2u) ? v.x : v.y;
    float a2 = (w0 == HW - 2u) ? v.w : v.z;
    float a3 = (w0 == HW - 4u) ? v.z : v.w;

    float4 r;
    r.x = a0 * bm.x;
    r.y = a1 * bm.y;
    r.z = a2 * bm.z;
    r.w = a3 * bm.w;
    __stcs(out + i, r);
}

extern "C" void kernel_launch(void* const* d_in, const int* in_sizes, int n_in,
                              void* d_out, int out_size)
{
    const float* x  = (const float*)d_in[0];
    const float* hm = (const float*)d_in[1];
    float* out = (float*)d_out;

    halo_call_kernel<<<TOTAL4 / 256u, 256>>>(x, (const float4*)hm, (float4*)out);
}